// round 15
// baseline (speedup 1.0000x reference)
#include <cuda_runtime.h>
#include <cuda_bf16.h>
#include <cstdint>

// AFM forward, algebraically collapsed (softmax over size-1 axis == 1):
//   x[b]   = 0.5*(||sum_f emb_f||^2 - sum_f ||emb_f||^2)
//   out[b] = sigmoid(x[b]*out_kernel + out_bias)
//
// FINAL (R15 == R11/R14, best measured 6.624us; 6.62-6.88 noise band).
// 14-round landscape: time is set by chip-level outstanding-miss
// concurrency on 106,496 random 64B transactions. Invariant to: warp
// shape (6 variants, 512..16384 warps), occupancy (6..73%), load flavor
// (LDG/.cg/.nc/cp.async.cg), fetch engine (LSU vs TMA split), L2 policy
// (evict_last), and DRAM byte volume (L2::64B halves traffic, time
// unchanged). Request count is minimal: one coalesced 64B transaction
// per (row,field) embedding.

#define B_ROWS   4096
#define N_SPARSE 26
#define VOCAB    100000

__device__ __forceinline__ float4 ldg_64b_v4(const float4* p) {
    float4 v;
    asm("ld.global.nc.L2::64B.v4.f32 {%0,%1,%2,%3}, [%4];"
        : "=f"(v.x), "=f"(v.y), "=f"(v.z), "=f"(v.w)
        : "l"(p));
    return v;
}

__global__ void __launch_bounds__(128) afm_gather_kernel(
    const int*    __restrict__ ids,     // [B, 26]
    const float4* __restrict__ table,   // [26, VOCAB, 4] float4 units
    const float*  __restrict__ out_k,   // [1]
    const float*  __restrict__ out_b,   // [1]
    float*        __restrict__ out)     // [B]
{
    const unsigned FULL = 0xffffffffu;
    const int gtid = blockIdx.x * blockDim.x + threadIdx.x;
    const int row  = gtid >> 5;            // one warp per row (grid exact)
    const int lane = threadIdx.x & 31;

    const int slice = lane & 3;            // float4 slice of the embedding
    const int fg    = lane >> 2;           // field-in-group 0..7

    const int* rid = ids + row * N_SPARSE;

    const float okv = __ldg(out_k);
    const float obv = __ldg(out_b);

    // Front-batched id loads: unconditional, clamped in-row (4-lane bcast,
    // 32B/warp/round; round-3 duplicate's gather is predicated off below).
    int idr[4];
    #pragma unroll
    for (int r = 0; r < 4; ++r) {
        int f = r * 8 + fg;
        idr[r] = __ldg(rid + (f < N_SPARSE ? f : N_SPARSE - 1));
    }

    float4 S = make_float4(0.f, 0.f, 0.f, 0.f);
    float  q = 0.f;

    // 4 independent 16B gathers per lane; each quad's 4x16B coalesce into
    // one 64B transaction per embedding. L2::64B limits the DRAM fetch to
    // the needed half-line (halves DRAM traffic vs default 128B fill).
    #pragma unroll
    for (int r = 0; r < 4; ++r) {
        const int f = r * 8 + fg;
        if (f < N_SPARSE) {
            const float4 v = ldg_64b_v4(table + (size_t)f * (VOCAB * 4)
                                              + (size_t)idr[r] * 4 + slice);
            S.x += v.x; S.y += v.y; S.z += v.z; S.w += v.w;
            q   += v.x * v.x + v.y * v.y + v.z * v.z + v.w * v.w;
        }
    }

    // Reduce S and q over the field dimension (lane bits 2,3,4).
    #pragma unroll
    for (int d = 4; d <= 16; d <<= 1) {
        S.x += __shfl_xor_sync(FULL, S.x, d);
        S.y += __shfl_xor_sync(FULL, S.y, d);
        S.z += __shfl_xor_sync(FULL, S.z, d);
        S.w += __shfl_xor_sync(FULL, S.w, d);
        q   += __shfl_xor_sync(FULL, q, d);
    }

    // Lanes 0..3 hold per-slice totals. Merged tail: per-slice partial
    // t = |S_slice|^2 - q_slice, then one 2-level reduction over slices.
    float t = S.x * S.x + S.y * S.y + S.z * S.z + S.w * S.w - q;
    t += __shfl_xor_sync(FULL, t, 1);
    t += __shfl_xor_sync(FULL, t, 2);

    if (lane == 0) {
        const float z = 0.5f * t * okv + obv;   // t == 2*sum_{i<j} e_i.e_j
        out[row] = 1.0f / (1.0f + __expf(-z));
    }
}

extern "C" void kernel_launch(void* const* d_in, const int* in_sizes, int n_in,
                              void* d_out, int out_size)
{
    (void)in_sizes; (void)n_in; (void)out_size;
    const int*    ids   = (const int*)   d_in[1];
    const float4* table = (const float4*)d_in[2];
    const float*  out_k = (const float*) d_in[7];
    const float*  out_b = (const float*) d_in[8];
    float*        out   = (float*)       d_out;

    const int threads = 128;                     // 4 warps = 4 rows / block
    const int blocks  = (B_ROWS * 32) / threads; // 1024 blocks, exact
    afm_gather_kernel<<<blocks, threads>>>(ids, table, out_k, out_b, out);
}

// round 16
// speedup vs baseline: 1.0337x; 1.0337x over previous
#include <cuda_runtime.h>
#include <cuda_bf16.h>
#include <cstdint>

// AFM forward, algebraically collapsed (softmax over size-1 axis == 1):
//   x[b]   = 0.5*(||sum_f emb_f||^2 - sum_f ||emb_f||^2)
//   out[b] = sigmoid(x[b]*out_kernel + out_bias)
//
// FINAL. Best measured 6.624us (noise band 6.62-6.88 over 4 benches of
// this source). 15-round landscape: time is set by chip-level
// outstanding-miss concurrency on 106,496 random 64B transactions --
// invariant to warp shape (512..16384 warps), occupancy (6..73%), load
// flavor (LDG/.cg/.nc/cp.async.cg), fetch engine (LSU vs TMA split),
// L2 policy (evict_last), and DRAM byte volume (L2::64B halves traffic
// at unchanged time). Request count is minimal: one coalesced 64B
// transaction per (row,field) embedding.
//
// Shape: ONE WARP PER ROW, 1024 CTAs x 128 threads, front-batched
// broadcast id loads, L2::64B fetch hint, merged 17-shuffle tail.

#define B_ROWS   4096
#define N_SPARSE 26
#define VOCAB    100000

__device__ __forceinline__ float4 ldg_64b_v4(const float4* p) {
    float4 v;
    asm("ld.global.nc.L2::64B.v4.f32 {%0,%1,%2,%3}, [%4];"
        : "=f"(v.x), "=f"(v.y), "=f"(v.z), "=f"(v.w)
        : "l"(p));
    return v;
}

__global__ void __launch_bounds__(128) afm_gather_kernel(
    const int*    __restrict__ ids,     // [B, 26]
    const float4* __restrict__ table,   // [26, VOCAB, 4] float4 units
    const float*  __restrict__ out_k,   // [1]
    const float*  __restrict__ out_b,   // [1]
    float*        __restrict__ out)     // [B]
{
    const unsigned FULL = 0xffffffffu;
    const int gtid = blockIdx.x * blockDim.x + threadIdx.x;
    const int row  = gtid >> 5;            // one warp per row (grid exact)
    const int lane = threadIdx.x & 31;

    const int slice = lane & 3;            // float4 slice of the embedding
    const int fg    = lane >> 2;           // field-in-group 0..7

    const int* rid = ids + row * N_SPARSE;

    const float okv = __ldg(out_k);
    const float obv = __ldg(out_b);

    // Front-batched id loads: unconditional, clamped in-row (4-lane bcast,
    // 32B/warp/round; round-3 duplicate's gather is predicated off below).
    int idr[4];
    #pragma unroll
    for (int r = 0; r < 4; ++r) {
        int f = r * 8 + fg;
        idr[r] = __ldg(rid + (f < N_SPARSE ? f : N_SPARSE - 1));
    }

    float4 S = make_float4(0.f, 0.f, 0.f, 0.f);
    float  q = 0.f;

    // 4 independent 16B gathers per lane; each quad's 4x16B coalesce into
    // one 64B transaction per embedding. L2::64B limits the DRAM fetch to
    // the needed half-line (halves DRAM traffic vs default 128B fill).
    #pragma unroll
    for (int r = 0; r < 4; ++r) {
        const int f = r * 8 + fg;
        if (f < N_SPARSE) {
            const float4 v = ldg_64b_v4(table + (size_t)f * (VOCAB * 4)
                                              + (size_t)idr[r] * 4 + slice);
            S.x += v.x; S.y += v.y; S.z += v.z; S.w += v.w;
            q   += v.x * v.x + v.y * v.y + v.z * v.z + v.w * v.w;
        }
    }

    // Reduce S and q over the field dimension (lane bits 2,3,4).
    #pragma unroll
    for (int d = 4; d <= 16; d <<= 1) {
        S.x += __shfl_xor_sync(FULL, S.x, d);
        S.y += __shfl_xor_sync(FULL, S.y, d);
        S.z += __shfl_xor_sync(FULL, S.z, d);
        S.w += __shfl_xor_sync(FULL, S.w, d);
        q   += __shfl_xor_sync(FULL, q, d);
    }

    // Lanes 0..3 hold per-slice totals. Merged tail: per-slice partial
    // t = |S_slice|^2 - q_slice, then one 2-level reduction over slices.
    float t = S.x * S.x + S.y * S.y + S.z * S.z + S.w * S.w - q;
    t += __shfl_xor_sync(FULL, t, 1);
    t += __shfl_xor_sync(FULL, t, 2);

    if (lane == 0) {
        const float z = 0.5f * t * okv + obv;   // t == 2*sum_{i<j} e_i.e_j
        out[row] = 1.0f / (1.0f + __expf(-z));
    }
}

extern "C" void kernel_launch(void* const* d_in, const int* in_sizes, int n_in,
                              void* d_out, int out_size)
{
    (void)in_sizes; (void)n_in; (void)out_size;
    const int*    ids   = (const int*)   d_in[1];
    const float4* table = (const float4*)d_in[2];
    const float*  out_k = (const float*) d_in[7];
    const float*  out_b = (const float*) d_in[8];
    float*        out   = (float*)       d_out;

    const int threads = 128;                     // 4 warps = 4 rows / block
    const int blocks  = (B_ROWS * 32) / threads; // 1024 blocks, exact
    afm_gather_kernel<<<blocks, threads>>>(ids, table, out_k, out_b, out);
}